// round 14
// baseline (speedup 1.0000x reference)
#include <cuda_runtime.h>
#include <cuda_bf16.h>
#include <cstdint>

#define N_NODES  50000
#define N_EDGES  600000
#define N_GRAPHS 256
#define C        128
#define NT       196     // ceil(50000/256) M-tiles of 256 rows
#define GGRID    152     // GB300: 152 SMs, 1 CTA/SM

// ---------------- scratch (device globals; no allocations allowed) ----------
__device__ int   d_deg[N_NODES];
__device__ int   d_rowptr[N_NODES + 1];
__device__ int   d_fill[N_NODES];
__device__ int   d_esrc[N_EDGES];
__device__ float d_deginv[N_NODES];

// activations, packed: per k-pair one uint2 {x = bf16 hi-pair, y = bf16 lo-pair}
__device__ uint2 d_xP[N_NODES * 64];
__device__ uint2 d_aggP[N_NODES * 64];
__device__ uint2 d_h0P[N_NODES * 64];
__device__ uint2 d_h1P[N_NODES * 64];
// fp32 copies for aggregation gather + readout
__device__ float d_h0f[N_NODES * C];
__device__ float d_h1f[N_NODES * C];

// weights: [k][co] K-major concat (k<128 -> W_l, k>=128 -> W_r)
__device__ __nv_bfloat16 d_WTh[4][256 * 128];
__device__ __nv_bfloat16 d_WTl[4][256 * 128];
__device__ float d_gsum[N_GRAPHS * C];
__device__ float d_gcnt[N_GRAPHS];

// ---------------- helpers ----------------------------------------------------
__device__ __forceinline__ void split_bf16(float x, __nv_bfloat16& h, __nv_bfloat16& l) {
    h = __float2bfloat16(x);
    l = __float2bfloat16(x - __bfloat162float(h));
}

__device__ __forceinline__ uint32_t smem_u32(const void* p) {
    return (uint32_t)__cvta_generic_to_shared(p);
}

__device__ __forceinline__ void ldmBT4(uint32_t* r, uint32_t addr) {
    asm volatile("ldmatrix.sync.aligned.m8n8.x4.trans.shared.b16 {%0,%1,%2,%3}, [%4];"
                 : "=r"(r[0]), "=r"(r[1]), "=r"(r[2]), "=r"(r[3]) : "r"(addr));
}

__device__ __forceinline__ void mma16816(float* c, const uint32_t* a, const uint32_t* b) {
    asm volatile(
        "mma.sync.aligned.m16n8k16.row.col.f32.bf16.bf16.f32 "
        "{%0,%1,%2,%3}, {%4,%5,%6,%7}, {%8,%9}, {%0,%1,%2,%3};"
        : "+f"(c[0]), "+f"(c[1]), "+f"(c[2]), "+f"(c[3])
        : "r"(a[0]), "r"(a[1]), "r"(a[2]), "r"(a[3]), "r"(b[0]), "r"(b[1]));
}

__device__ __forceinline__ void cpa16(uint32_t smem, const void* g) {
    asm volatile("cp.async.cg.shared.global [%0], [%1], 16;"
                 :: "r"(smem), "l"(g) : "memory");
}

__device__ __forceinline__ uint32_t pack2(float a, float b, float& la, float& lb) {
    __nv_bfloat16 ha = __float2bfloat16(a);
    __nv_bfloat16 hb = __float2bfloat16(b);
    la = a - __bfloat162float(ha);
    lb = b - __bfloat162float(hb);
    __nv_bfloat162 t = __halves2bfloat162(ha, hb);
    return *reinterpret_cast<uint32_t*>(&t);
}

// ---------------- fused preprocessing: hist + xsplit + wsplit ----------------
#define HB 2344
#define XB 1024
#define WB 512
__global__ void k_prep(const int* __restrict__ tgt, const float* __restrict__ x,
                       const float* __restrict__ wl0, const float* __restrict__ wr0,
                       const float* __restrict__ wl1, const float* __restrict__ wr1,
                       const float* __restrict__ wl2, const float* __restrict__ wr2,
                       const float* __restrict__ wl3, const float* __restrict__ wr3)
{
    int bid = blockIdx.x;
    int tid = threadIdx.x;
    if (bid < HB) {
        int e = bid * 256 + tid;
        if (e < N_EDGES) atomicAdd(&d_deg[tgt[e]], 1);
    } else if (bid < HB + XB) {
        int gid = (bid - HB) * 256 + tid;
        for (int j = gid; j < N_NODES * 64; j += XB * 256) {
            float2 v = ((const float2*)x)[j];
            float lx, ly;
            uint32_t hp = pack2(v.x, v.y, lx, ly);
            __nv_bfloat162 lp = __halves2bfloat162(__float2bfloat16(lx), __float2bfloat16(ly));
            d_xP[j] = make_uint2(hp, *reinterpret_cast<uint32_t*>(&lp));
        }
    } else {
        int idx = (bid - HB - XB) * 256 + tid;   // < 4*256*128
        int layer = idx >> 15;
        int rem = idx & 32767;
        int k  = rem >> 7;     // 0..255
        int co = rem & 127;    // 0..127
        const float* wl = (layer == 0) ? wl0 : (layer == 1) ? wl1 : (layer == 2) ? wl2 : wl3;
        const float* wr = (layer == 0) ? wr0 : (layer == 1) ? wr1 : (layer == 2) ? wr2 : wr3;
        float v = (k < 128) ? wl[co * 128 + k] : wr[co * 128 + (k - 128)];
        __nv_bfloat16 h, l;
        split_bf16(v, h, l);
        d_WTh[layer][k * 128 + co] = h;
        d_WTl[layer][k * 128 + co] = l;
    }
}

// ---------------- exclusive scan --------------------------------------------
__global__ void k_scan() {
    __shared__ int sums[1024];
    const int CH = (N_NODES + 1023) / 1024;
    int t = threadIdx.x;
    int base = t * CH;
    int s = 0;
    for (int i = base; i < base + CH && i < N_NODES; i++) s += d_deg[i];
    sums[t] = s;
    __syncthreads();
    for (int off = 1; off < 1024; off <<= 1) {
        int v = 0;
        if (t >= off) v = sums[t - off];
        __syncthreads();
        if (t >= off) sums[t] += v;
        __syncthreads();
    }
    int run = (t > 0) ? sums[t - 1] : 0;
    for (int i = base; i < base + CH && i < N_NODES; i++) {
        d_rowptr[i] = run;
        int dg = d_deg[i];
        d_deginv[i] = 1.0f / (float)max(dg, 1);
        run += dg;
    }
    if (N_NODES >= base && N_NODES < base + CH) d_rowptr[N_NODES] = run;
}

// ---------------- CSR fill ---------------------------------------------------
__global__ void k_fill(const int* __restrict__ src, const int* __restrict__ tgt) {
    int e = blockIdx.x * blockDim.x + threadIdx.x;
    if (e < N_EDGES) {
        int t = tgt[e];
        int slot = atomicAdd(&d_fill[t], 1);
        d_esrc[d_rowptr[t] + slot] = src[e];
    }
}

// ---------------- mean aggregation: warp per node, MLP-8, packed output ------
__global__ __launch_bounds__(256) void k_agg(const float* __restrict__ xf, int insel) {
    const float* xin = (insel == 0) ? xf : ((insel == 1) ? d_h0f : d_h1f);

    int wid  = threadIdx.x >> 5;
    int lane = threadIdx.x & 31;
    int n = blockIdx.x * 8 + wid;
    if (n >= N_NODES) return;
    int ch = lane * 4;
    int s0 = d_rowptr[n], s1 = d_rowptr[n + 1];
    float a0 = 0.f, a1 = 0.f, a2 = 0.f, a3 = 0.f;

    for (int base = s0; base < s1; base += 8) {
        int m = s1 - base;
        int idx = 0;
        if (lane < 8 && lane < m) idx = __ldg(&d_esrc[base + lane]);
        float4 v[8];
        int srcs[8];
        #pragma unroll
        for (int j = 0; j < 8; j++)
            srcs[j] = __shfl_sync(0xffffffffu, idx, j);
        #pragma unroll
        for (int j = 0; j < 8; j++) {
            if (j < m)
                v[j] = __ldg((const float4*)&xin[(size_t)srcs[j] * C + ch]);
            else
                v[j] = make_float4(0.f, 0.f, 0.f, 0.f);
        }
        #pragma unroll
        for (int j = 0; j < 8; j++) {
            a0 += v[j].x; a1 += v[j].y; a2 += v[j].z; a3 += v[j].w;
        }
    }

    float di = d_deginv[n];
    a0 *= di; a1 *= di; a2 *= di; a3 *= di;
    __nv_bfloat16 h0, l0, h1, l1, h2, l2, h3, l3;
    split_bf16(a0, h0, l0); split_bf16(a1, h1, l1);
    split_bf16(a2, h2, l2); split_bf16(a3, h3, l3);
    __nv_bfloat162 t01h = __halves2bfloat162(h0, h1), t01l = __halves2bfloat162(l0, l1);
    __nv_bfloat162 t23h = __halves2bfloat162(h2, h3), t23l = __halves2bfloat162(l2, l3);
    uint4 o;
    o.x = *reinterpret_cast<uint32_t*>(&t01h);
    o.y = *reinterpret_cast<uint32_t*>(&t01l);
    o.z = *reinterpret_cast<uint32_t*>(&t23h);
    o.w = *reinterpret_cast<uint32_t*>(&t23l);
    *(uint4*)&d_aggP[(size_t)n * 64 + lane * 2] = o;
}

// ---------------- SAGE linear: W-resident persistent GEMM --------------------
// grid=152, 512thr, 1 CTA/SM. Full W hi/lo resident in smem (139KB, once per
// CTA). A fragments loaded direct from gmem via packed LDG.64. No k-loop
// barriers. BM=256 per tile, warp tile m32 x n64, 3-term bf16 split mma.
#define WSTR 136
#define WL_OFF (256 * WSTR)
#define GEMM_SMEM_B (2 * 256 * WSTR * 2)   // 139264 bytes

__global__ __launch_bounds__(512, 1) void k_gemm(
    int insel, int outsel, int layer, const float* __restrict__ bias)
{
    const uint2* XP = (insel == 0) ? d_xP : (insel == 1) ? d_h0P : d_h1P;
    uint2* outP = (outsel == 1) ? d_h0P : d_h1P;
    float* outf = (outsel == 1) ? d_h0f : d_h1f;
    const __nv_bfloat16* WTh = d_WTh[layer];
    const __nv_bfloat16* WTl = d_WTl[layer];

    extern __shared__ __align__(16) __nv_bfloat16 sm[];

    int tid  = threadIdx.x;
    int lane = tid & 31;
    int wid  = tid >> 5;           // 0..15
    int warp_m = wid >> 1;         // 8 m-warps (32 rows each)
    int warp_n = wid & 1;          // 2 n-warps (64 cols each)

    // ---- stage full W (hi+lo) into smem: 8 commit groups of k32 each --------
    // per group: 2 arrays x 32 rows x 16 chunks(16B) = 1024 granules,
    // 512 threads x 2 each. FULL row coverage (R13 bug: only half the row).
    {
        #pragma unroll
        for (int g = 0; g < 8; g++) {
            #pragma unroll
            for (int q = 0; q < 2; q++) {
                int gid = tid + q * 512;       // 0..1023
                int arr = gid >> 9;            // 0 hi, 1 lo
                int rem = gid & 511;
                int r   = rem >> 4;            // 0..31
                int j   = rem & 15;            // 0..15  (16 x 8 el = 128 el row)
                int krow = g * 32 + r;
                const __nv_bfloat16* s = (arr ? WTl : WTh) + krow * 128 + j * 8;
                uint32_t dst = smem_u32(&sm[(arr ? WL_OFF : 0) + krow * WSTR + j * 8]);
                cpa16(dst, s);
            }
            asm volatile("cp.async.commit_group;" ::: "memory");
        }
    }

    int bcol = warp_n * 64 + (lane >> 4) * 8;
    int wrow_lane = (lane & 15);

    for (int mt = blockIdx.x; mt < NT; mt += GGRID) {
        int rB = mt * 256 + warp_m * 32 + (lane >> 2);
        bool pr0 = rB      < N_NODES;
        bool pr1 = rB + 8  < N_NODES;
        bool pr2 = rB + 16 < N_NODES;
        bool pr3 = rB + 24 < N_NODES;

        float acc[2][8][4];
        #pragma unroll
        for (int mi = 0; mi < 2; mi++)
            #pragma unroll
            for (int ni = 0; ni < 8; ni++)
                #pragma unroll
                for (int q = 0; q < 4; q++) acc[mi][ni][q] = 0.f;

        auto kstep = [&](const uint2* __restrict__ AP, int jw, int jk) {
            int kp = jk * 8 + (lane & 3);
            uint32_t ah[2][4], al[2][4];
            #pragma unroll
            for (int mi = 0; mi < 2; mi++) {
                int r0 = rB + mi * 16;
                bool pa = mi ? pr2 : pr0;
                bool pb = mi ? pr3 : pr1;
                uint2 z = make_uint2(0u, 0u);
                uint2 u00 = pa ? __ldg(&AP[(size_t)r0 * 64 + kp])           : z;
                uint2 u10 = pb ? __ldg(&AP[(size_t)(r0 + 8) * 64 + kp])     : z;
                uint2 u01 = pa ? __ldg(&AP[(size_t)r0 * 64 + kp + 4])       : z;
                uint2 u11 = pb ? __ldg(&AP[(size_t)(r0 + 8) * 64 + kp + 4]) : z;
                ah[mi][0] = u00.x; ah[mi][1] = u10.x; ah[mi][2] = u01.x; ah[mi][3] = u11.x;
                al[mi][0] = u00.y; al[mi][1] = u10.y; al[mi][2] = u01.y; al[mi][3] = u11.y;
            }
            int wr = (jw * 16 + wrow_lane) * WSTR + bcol;
            #pragma unroll
            for (int np = 0; np < 4; np++) {
                uint32_t th[4], tl[4];
                ldmBT4(th, smem_u32(&sm[wr + np * 16]));
                ldmBT4(tl, smem_u32(&sm[WL_OFF + wr + np * 16]));
                uint32_t b0h[2] = {th[0], th[1]}, b1h[2] = {th[2], th[3]};
                uint32_t b0l[2] = {tl[0], tl[1]}, b1l[2] = {tl[2], tl[3]};
                #pragma unroll
                for (int mi = 0; mi < 2; mi++) {
                    mma16816(acc[mi][np * 2],     ah[mi], b0h);
                    mma16816(acc[mi][np * 2],     ah[mi], b0l);
                    mma16816(acc[mi][np * 2],     al[mi], b0h);
                    mma16816(acc[mi][np * 2 + 1], ah[mi], b1h);
                    mma16816(acc[mi][np * 2 + 1], ah[mi], b1l);
                    mma16816(acc[mi][np * 2 + 1], al[mi], b1h);
                }
            }
        };

        // k 0..127 from agg (needs W groups 0..3)
        asm volatile("cp.async.wait_group 4;" ::: "memory");
        __syncthreads();
        #pragma unroll
        for (int j = 0; j < 8; j++) kstep(d_aggP, j, j);
        // k 128..255 from x/h (needs all W groups)
        asm volatile("cp.async.wait_group 0;" ::: "memory");
        __syncthreads();
        #pragma unroll
        for (int j = 8; j < 16; j++) kstep(XP, j, j - 8);

        // ---- epilogue: bias + relu + split + packed store -------------------
        #pragma unroll
        for (int mi = 0; mi < 2; mi++) {
            #pragma unroll
            for (int ni = 0; ni < 8; ni++) {
                int cc = warp_n * 64 + ni * 8 + (lane & 3) * 2;
                float b0 = __ldg(&bias[cc]);
                float b1 = __ldg(&bias[cc + 1]);
                int r0 = rB + mi * 16;
                bool pa = mi ? pr2 : pr0;
                bool pb = mi ? pr3 : pr1;
                if (pa) {
                    float vx = fmaxf(acc[mi][ni][0] + b0, 0.f);
                    float vy = fmaxf(acc[mi][ni][1] + b1, 0.f);
                    __nv_bfloat16 hx, lx, hy, ly;
                    split_bf16(vx, hx, lx); split_bf16(vy, hy, ly);
                    __nv_bfloat162 hp = __halves2bfloat162(hx, hy);
                    __nv_bfloat162 lp = __halves2bfloat162(lx, ly);
                    outP[(size_t)r0 * 64 + (cc >> 1)] =
                        make_uint2(*reinterpret_cast<uint32_t*>(&hp),
                                   *reinterpret_cast<uint32_t*>(&lp));
                    *(float2*)&outf[(size_t)r0 * C + cc] = make_float2(vx, vy);
                }
                if (pb) {
                    int r1 = r0 + 8;
                    float vx = fmaxf(acc[mi][ni][2] + b0, 0.f);
                    float vy = fmaxf(acc[mi][ni][3] + b1, 0.f);
                    __nv_bfloat16 hx, lx, hy, ly;
                    split_bf16(vx, hx, lx); split_bf16(vy, hy, ly);
                    __nv_bfloat162 hp = __halves2bfloat162(hx, hy);
                    __nv_bfloat162 lp = __halves2bfloat162(lx, ly);
                    outP[(size_t)r1 * 64 + (cc >> 1)] =
                        make_uint2(*reinterpret_cast<uint32_t*>(&hp),
                                   *reinterpret_cast<uint32_t*>(&lp));
                    *(float2*)&outf[(size_t)r1 * C + cc] = make_float2(vx, vy);
                }
            }
        }
    }
}

// ---------------- graph mean pooling -----------------------------------------
__global__ void k_pool(const int* __restrict__ batch) {
    int n = blockIdx.x;
    int c = threadIdx.x;
    int g = batch[n];
    atomicAdd(&d_gsum[g * C + c], d_h1f[(size_t)n * C + c]);
    if (c == 0) atomicAdd(&d_gcnt[g], 1.0f);
}

// ---------------- classifier --------------------------------------------------
__global__ void k_final(const int* __restrict__ root,
                        const float* __restrict__ wcls,
                        const float* __restrict__ bcls,
                        float* __restrict__ out)
{
    int g = blockIdx.x;
    int c = threadIdx.x;
    int rn = root[g];
    float rv = d_h1f[(size_t)rn * C + c];
    float gm = d_gsum[g * C + c] / fmaxf(d_gcnt[g], 1.0f);
    __shared__ float red[2][4];
    float p0 = rv * wcls[0 * 256 + c] + gm * wcls[0 * 256 + 128 + c];
    float p1 = rv * wcls[1 * 256 + c] + gm * wcls[1 * 256 + 128 + c];
    #pragma unroll
    for (int off = 16; off > 0; off >>= 1) {
        p0 += __shfl_down_sync(0xffffffffu, p0, off);
        p1 += __shfl_down_sync(0xffffffffu, p1, off);
    }
    if ((c & 31) == 0) { red[0][c >> 5] = p0; red[1][c >> 5] = p1; }
    __syncthreads();
    if (c == 0) {
        out[g * 2 + 0] = red[0][0] + red[0][1] + red[0][2] + red[0][3] + bcls[0];
        out[g * 2 + 1] = red[1][0] + red[1][1] + red[1][2] + red[1][3] + bcls[1];
    }
}

// ---------------- launch ------------------------------------------------------
extern "C" void kernel_launch(void* const* d_in, const int* in_sizes, int n_in,
                              void* d_out, int out_size)
{
    const float* x     = (const float*)d_in[0];
    const int*   eidx  = (const int*)d_in[1];
    const int*   src   = eidx;
    const int*   tgt   = eidx + N_EDGES;
    const int*   root  = (const int*)d_in[2];
    const int*   batch = (const int*)d_in[3];
    const float* wl[4] = {(const float*)d_in[4],  (const float*)d_in[7],
                          (const float*)d_in[10], (const float*)d_in[13]};
    const float* bl[4] = {(const float*)d_in[5],  (const float*)d_in[8],
                          (const float*)d_in[11], (const float*)d_in[14]};
    const float* wr[4] = {(const float*)d_in[6],  (const float*)d_in[9],
                          (const float*)d_in[12], (const float*)d_in[15]};
    const float* wcls  = (const float*)d_in[16];
    const float* bcls  = (const float*)d_in[17];
    float* out = (float*)d_out;

    (void)in_sizes; (void)n_in; (void)out_size;

    static bool attr_set = false;
    static void *p_deg = nullptr, *p_fill = nullptr, *p_gsum = nullptr, *p_gcnt = nullptr;
    if (!attr_set) {
        cudaFuncSetAttribute(k_gemm, cudaFuncAttributeMaxDynamicSharedMemorySize, GEMM_SMEM_B);
        cudaGetSymbolAddress(&p_deg,  d_deg);
        cudaGetSymbolAddress(&p_fill, d_fill);
        cudaGetSymbolAddress(&p_gsum, d_gsum);
        cudaGetSymbolAddress(&p_gcnt, d_gcnt);
        attr_set = true;
    }

    cudaMemsetAsync(p_deg,  0, N_NODES * sizeof(int));
    cudaMemsetAsync(p_fill, 0, N_NODES * sizeof(int));
    cudaMemsetAsync(p_gsum, 0, N_GRAPHS * C * sizeof(float));
    cudaMemsetAsync(p_gcnt, 0, N_GRAPHS * sizeof(float));

    // 1-3: structure build
    k_prep<<<HB + XB + WB, 256>>>(tgt, x,
                                  wl[0], wr[0], wl[1], wr[1],
                                  wl[2], wr[2], wl[3], wr[3]);
    k_scan<<<1, 1024>>>();
    k_fill<<<(N_EDGES + 255) / 256, 256>>>(src, tgt);

    const int AGG_GRID = (N_NODES + 7) / 8;       // 6250

    // layers (launch 4 = first k_agg -> ncu capture slot)
    k_agg<<<AGG_GRID, 256>>>(x, 0);
    k_gemm<<<GGRID, 512, GEMM_SMEM_B>>>(0, 1, 0, bl[0]);
    k_agg<<<AGG_GRID, 256>>>(x, 1);
    k_gemm<<<GGRID, 512, GEMM_SMEM_B>>>(1, 2, 1, bl[1]);
    k_agg<<<AGG_GRID, 256>>>(x, 2);
    k_gemm<<<GGRID, 512, GEMM_SMEM_B>>>(2, 1, 2, bl[2]);
    k_agg<<<AGG_GRID, 256>>>(x, 1);
    k_gemm<<<GGRID, 512, GEMM_SMEM_B>>>(1, 2, 3, bl[3]);

    // readout
    k_pool<<<N_NODES, 128>>>(batch);
    k_final<<<N_GRAPHS, 128>>>(root, wcls, bcls, out);
}

// round 16
// speedup vs baseline: 1.1274x; 1.1274x over previous
#include <cuda_runtime.h>
#include <cuda_bf16.h>
#include <cstdint>

#define N_NODES  50000
#define N_EDGES  600000
#define N_GRAPHS 256
#define C        128
#define NT       391     // ceil(50000/128) M-tiles of 128 rows
#define GGRID    152     // GB300: 152 SMs, 1 CTA/SM

// ---------------- scratch (device globals; no allocations allowed) ----------
__device__ int   d_deg[N_NODES];
__device__ int   d_rowptr[N_NODES + 1];
__device__ int   d_fill[N_NODES];
__device__ int   d_esrc[N_EDGES];
__device__ float d_deginv[N_NODES];

// activations, packed + PERMUTED: row of 64 uint2 slots; pair p (= channels
// 2p,2p+1) lives at slot(p) = (p>>3)*8 + ((p&7)&3)*2 + ((p&7)>>2), so pairs
// q and q+4 of a 16-k step are ADJACENT -> one LDG.128 per A frag (hi+lo).
__device__ uint2 d_xP[N_NODES * 64];
__device__ uint2 d_aggP[N_NODES * 64];
__device__ uint2 d_h0P[N_NODES * 64];
__device__ uint2 d_h1P[N_NODES * 64];
// fp32 copies for aggregation gather + readout
__device__ float d_h0f[N_NODES * C];
__device__ float d_h1f[N_NODES * C];

// weights: [k][co] K-major concat (k<128 -> W_l, k>=128 -> W_r)
__device__ __nv_bfloat16 d_WTh[4][256 * 128];
__device__ __nv_bfloat16 d_WTl[4][256 * 128];
__device__ float d_gsum[N_GRAPHS * C];
__device__ float d_gcnt[N_GRAPHS];

// ---------------- helpers ----------------------------------------------------
__host__ __device__ __forceinline__ int pslot(int p) {
    int g = p >> 3, w = p & 7;
    return g * 8 + (w & 3) * 2 + (w >> 2);
}

__device__ __forceinline__ void split_bf16(float x, __nv_bfloat16& h, __nv_bfloat16& l) {
    h = __float2bfloat16(x);
    l = __float2bfloat16(x - __bfloat162float(h));
}

__device__ __forceinline__ uint32_t smem_u32(const void* p) {
    return (uint32_t)__cvta_generic_to_shared(p);
}

__device__ __forceinline__ void ldmBT4(uint32_t* r, uint32_t addr) {
    asm volatile("ldmatrix.sync.aligned.m8n8.x4.trans.shared.b16 {%0,%1,%2,%3}, [%4];"
                 : "=r"(r[0]), "=r"(r[1]), "=r"(r[2]), "=r"(r[3]) : "r"(addr));
}

__device__ __forceinline__ void mma16816(float* c, const uint32_t* a, const uint32_t* b) {
    asm volatile(
        "mma.sync.aligned.m16n8k16.row.col.f32.bf16.bf16.f32 "
        "{%0,%1,%2,%3}, {%4,%5,%6,%7}, {%8,%9}, {%0,%1,%2,%3};"
        : "+f"(c[0]), "+f"(c[1]), "+f"(c[2]), "+f"(c[3])
        : "r"(a[0]), "r"(a[1]), "r"(a[2]), "r"(a[3]), "r"(b[0]), "r"(b[1]));
}

__device__ __forceinline__ void cpa16(uint32_t smem, const void* g) {
    asm volatile("cp.async.cg.shared.global [%0], [%1], 16;"
                 :: "r"(smem), "l"(g) : "memory");
}

__device__ __forceinline__ uint2 mkpair(float a, float b) {
    __nv_bfloat16 ha, la, hb, lb;
    split_bf16(a, ha, la);
    split_bf16(b, hb, lb);
    __nv_bfloat162 hp = __halves2bfloat162(ha, hb);
    __nv_bfloat162 lp = __halves2bfloat162(la, lb);
    return make_uint2(*reinterpret_cast<uint32_t*>(&hp), *reinterpret_cast<uint32_t*>(&lp));
}

// ---------------- fused preprocessing: hist + xsplit + wsplit ----------------
#define HB 2344
#define XB 1024
#define WB 512
__global__ void k_prep(const int* __restrict__ tgt, const float* __restrict__ x,
                       const float* __restrict__ wl0, const float* __restrict__ wr0,
                       const float* __restrict__ wl1, const float* __restrict__ wr1,
                       const float* __restrict__ wl2, const float* __restrict__ wr2,
                       const float* __restrict__ wl3, const float* __restrict__ wr3)
{
    int bid = blockIdx.x;
    int tid = threadIdx.x;
    if (bid < HB) {
        int e = bid * 256 + tid;
        if (e < N_EDGES) atomicAdd(&d_deg[tgt[e]], 1);
    } else if (bid < HB + XB) {
        int gid = (bid - HB) * 256 + tid;
        for (int j = gid; j < N_NODES * 64; j += XB * 256) {
            int row = j >> 6, p = j & 63;
            float2 v = ((const float2*)x)[j];
            d_xP[row * 64 + pslot(p)] = mkpair(v.x, v.y);
        }
    } else {
        int idx = (bid - HB - XB) * 256 + tid;   // < 4*256*128
        int layer = idx >> 15;
        int rem = idx & 32767;
        int k  = rem >> 7;     // 0..255
        int co = rem & 127;    // 0..127
        const float* wl = (layer == 0) ? wl0 : (layer == 1) ? wl1 : (layer == 2) ? wl2 : wl3;
        const float* wr = (layer == 0) ? wr0 : (layer == 1) ? wr1 : (layer == 2) ? wr2 : wr3;
        float v = (k < 128) ? wl[co * 128 + k] : wr[co * 128 + (k - 128)];
        __nv_bfloat16 h, l;
        split_bf16(v, h, l);
        d_WTh[layer][k * 128 + co] = h;
        d_WTl[layer][k * 128 + co] = l;
    }
}

// ---------------- exclusive scan --------------------------------------------
__global__ void k_scan() {
    __shared__ int sums[1024];
    const int CH = (N_NODES + 1023) / 1024;
    int t = threadIdx.x;
    int base = t * CH;
    int s = 0;
    for (int i = base; i < base + CH && i < N_NODES; i++) s += d_deg[i];
    sums[t] = s;
    __syncthreads();
    for (int off = 1; off < 1024; off <<= 1) {
        int v = 0;
        if (t >= off) v = sums[t - off];
        __syncthreads();
        if (t >= off) sums[t] += v;
        __syncthreads();
    }
    int run = (t > 0) ? sums[t - 1] : 0;
    for (int i = base; i < base + CH && i < N_NODES; i++) {
        d_rowptr[i] = run;
        int dg = d_deg[i];
        d_deginv[i] = 1.0f / (float)max(dg, 1);
        run += dg;
    }
    if (N_NODES >= base && N_NODES < base + CH) d_rowptr[N_NODES] = run;
}

// ---------------- CSR fill ---------------------------------------------------
__global__ void k_fill(const int* __restrict__ src, const int* __restrict__ tgt) {
    int e = blockIdx.x * blockDim.x + threadIdx.x;
    if (e < N_EDGES) {
        int t = tgt[e];
        int slot = atomicAdd(&d_fill[t], 1);
        d_esrc[d_rowptr[t] + slot] = src[e];
    }
}

// ---------------- mean aggregation: warp per node, fp32 gather ---------------
__global__ __launch_bounds__(256) void k_agg(const float* __restrict__ xf, int insel) {
    const float* xin = (insel == 0) ? xf : ((insel == 1) ? d_h0f : d_h1f);

    int wid  = threadIdx.x >> 5;
    int lane = threadIdx.x & 31;
    int n = blockIdx.x * 8 + wid;
    if (n >= N_NODES) return;
    int ch = lane * 4;
    int s0 = d_rowptr[n], s1 = d_rowptr[n + 1];
    float a0 = 0.f, a1 = 0.f, a2 = 0.f, a3 = 0.f;
    #pragma unroll 2
    for (int e = s0; e < s1; e++) {
        int s = __ldg(&d_esrc[e]);
        float4 v = __ldg((const float4*)&xin[(size_t)s * C + ch]);
        a0 += v.x; a1 += v.y; a2 += v.z; a3 += v.w;
    }
    float di = d_deginv[n];
    a0 *= di; a1 *= di; a2 *= di; a3 *= di;
    // pairs 2*lane (ch 4l,4l+1) and 2*lane+1 (ch 4l+2,4l+3), permuted slots
    d_aggP[(size_t)n * 64 + pslot(2 * lane)]     = mkpair(a0, a1);
    d_aggP[(size_t)n * 64 + pslot(2 * lane + 1)] = mkpair(a2, a3);
}

// ---------------- SAGE linear: W-resident persistent GEMM (BM=128) ----------
// grid=152, 512thr, 1 CTA/SM. Full W hi/lo resident (139KB, loaded once).
// A frags direct from gmem: 2 x LDG.128 per thread per kstep (permuted pack).
// Warp tile m16 x n64, zero barriers in the tile loop, A prefetch depth 1.
#define WSTR 136
#define WL_OFF (256 * WSTR)
#define GEMM_SMEM_B (2 * 256 * WSTR * 2)   // 139264 bytes

__global__ __launch_bounds__(512, 1) void k_gemm(
    int insel, int outsel, int layer, const float* __restrict__ bias)
{
    const uint2* XP = (insel == 0) ? d_xP : (insel == 1) ? d_h0P : d_h1P;
    uint2* outP = (outsel == 1) ? d_h0P : d_h1P;
    float* outf = (outsel == 1) ? d_h0f : d_h1f;
    const __nv_bfloat16* WTh = d_WTh[layer];
    const __nv_bfloat16* WTl = d_WTl[layer];

    extern __shared__ __align__(16) __nv_bfloat16 sm[];

    int tid  = threadIdx.x;
    int lane = tid & 31;
    int wid  = tid >> 5;           // 0..15
    int warp_m = wid >> 1;         // 8 m-warps (16 rows each)
    int warp_n = wid & 1;          // 2 n-warps (64 cols each)
    int q = lane & 3;

    // ---- stage full W (hi+lo): 2 arrays x 256 rows x 16 chunks = 8192 -------
    for (int g = tid; g < 8192; g += 512) {
        int arr = g >> 12;
        int rem = g & 4095;
        int r   = rem >> 4;
        int j   = rem & 15;
        const __nv_bfloat16* s = (arr ? WTl : WTh) + r * 128 + j * 8;
        uint32_t dst = smem_u32(&sm[(arr ? WL_OFF : 0) + r * WSTR + j * 8]);
        cpa16(dst, s);
    }
    asm volatile("cp.async.commit_group;" ::: "memory");

    // bias -> registers (constant across tiles)
    float breg[8][2];
    #pragma unroll
    for (int ni = 0; ni < 8; ni++) {
        int cc = warp_n * 64 + ni * 8 + q * 2;
        breg[ni][0] = __ldg(&bias[cc]);
        breg[ni][1] = __ldg(&bias[cc + 1]);
    }
    // output pair slots (constant across tiles)
    int oslot[8];
    #pragma unroll
    for (int ni = 0; ni < 8; ni++)
        oslot[ni] = pslot(warp_n * 32 + ni * 4 + q);

    int bcol = warp_n * 64 + (lane >> 4) * 8;
    int wrow_lane = lane & 15;

    asm volatile("cp.async.wait_group 0;" ::: "memory");
    __syncthreads();

    for (int mt = blockIdx.x; mt < NT; mt += GGRID) {
        int r0 = mt * 128 + warp_m * 16 + (lane >> 2);
        bool pa = r0     < N_NODES;
        bool pb = r0 + 8 < N_NODES;
        const uint2* rowA = pa ? (d_aggP + (size_t)r0 * 64)       : d_aggP;
        const uint2* rowB = pb ? (d_aggP + (size_t)(r0 + 8) * 64) : d_aggP;
        const uint2* rowAx = pa ? (XP + (size_t)r0 * 64)       : XP;
        const uint2* rowBx = pb ? (XP + (size_t)(r0 + 8) * 64) : XP;

        float acc[8][4];
        #pragma unroll
        for (int ni = 0; ni < 8; ni++)
            #pragma unroll
            for (int t2 = 0; t2 < 4; t2++) acc[ni][t2] = 0.f;

        // prologue: kstep 0 A frags
        uint4 u = pa ? __ldg((const uint4*)(rowA + 2 * q)) : make_uint4(0,0,0,0);
        uint4 v = pb ? __ldg((const uint4*)(rowB + 2 * q)) : make_uint4(0,0,0,0);

        #pragma unroll
        for (int jw = 0; jw < 16; jw++) {
            // prefetch next kstep
            uint4 un = make_uint4(0,0,0,0), vn = make_uint4(0,0,0,0);
            if (jw < 15) {
                int jn = jw + 1;
                const uint2* ra = (jn < 8) ? rowA : rowAx;
                const uint2* rb = (jn < 8) ? rowB : rowBx;
                int off = (jn & 7) * 8 + 2 * q;
                if (pa) un = __ldg((const uint4*)(ra + off));
                if (pb) vn = __ldg((const uint4*)(rb + off));
            }

            uint32_t ah[4] = {u.x, v.x, u.z, v.z};
            uint32_t al[4] = {u.y, v.y, u.w, v.w};

            int wr = (jw * 16 + wrow_lane) * WSTR + bcol;
            #pragma unroll
            for (int np = 0; np < 4; np++) {
                uint32_t th[4], tl[4];
                ldmBT4(th, smem_u32(&sm[wr + np * 16]));
                ldmBT4(tl, smem_u32(&sm[WL_OFF + wr + np * 16]));
                uint32_t b0h[2] = {th[0], th[1]}, b1h[2] = {th[2], th[3]};
                uint32_t b0l[2] = {tl[0], tl[1]}, b1l[2] = {tl[2], tl[3]};
                mma16816(acc[np * 2],     ah, b0h);
                mma16816(acc[np * 2],     ah, b0l);
                mma16816(acc[np * 2],     al, b0h);
                mma16816(acc[np * 2 + 1], ah, b1h);
                mma16816(acc[np * 2 + 1], ah, b1l);
                mma16816(acc[np * 2 + 1], al, b1h);
            }
            u = un; v = vn;
        }

        // ---- epilogue: bias + relu + split + permuted packed store ----------
        #pragma unroll
        for (int ni = 0; ni < 8; ni++) {
            int cc = warp_n * 64 + ni * 8 + q * 2;
            if (pa) {
                float vx = fmaxf(acc[ni][0] + breg[ni][0], 0.f);
                float vy = fmaxf(acc[ni][1] + breg[ni][1], 0.f);
                outP[(size_t)r0 * 64 + oslot[ni]] = mkpair(vx, vy);
                *(float2*)&outf[(size_t)r0 * C + cc] = make_float2(vx, vy);
            }
            if (pb) {
                int r1 = r0 + 8;
                float vx = fmaxf(acc[ni][2] + breg[ni][0], 0.f);
                float vy = fmaxf(acc[ni][3] + breg[ni][1], 0.f);
                outP[(size_t)r1 * 64 + oslot[ni]] = mkpair(vx, vy);
                *(float2*)&outf[(size_t)r1 * C + cc] = make_float2(vx, vy);
            }
        }
    }
}

// ---------------- graph mean pooling -----------------------------------------
__global__ void k_pool(const int* __restrict__ batch) {
    int n = blockIdx.x;
    int c = threadIdx.x;
    int g = batch[n];
    atomicAdd(&d_gsum[g * C + c], d_h1f[(size_t)n * C + c]);
    if (c == 0) atomicAdd(&d_gcnt[g], 1.0f);
}

// ---------------- classifier --------------------------------------------------
__global__ void k_final(const int* __restrict__ root,
                        const float* __restrict__ wcls,
                        const float* __restrict__ bcls,
                        float* __restrict__ out)
{
    int g = blockIdx.x;
    int c = threadIdx.x;
    int rn = root[g];
    float rv = d_h1f[(size_t)rn * C + c];
    float gm = d_gsum[g * C + c] / fmaxf(d_gcnt[g], 1.0f);
    __shared__ float red[2][4];
    float p0 = rv * wcls[0 * 256 + c] + gm * wcls[0 * 256 + 128 + c];
    float p1 = rv * wcls[1 * 256 + c] + gm * wcls[1 * 256 + 128 + c];
    #pragma unroll
    for (int off = 16; off > 0; off >>= 1) {
        p0 += __shfl_down_sync(0xffffffffu, p0, off);
        p1 += __shfl_down_sync(0xffffffffu, p1, off);
    }
    if ((c & 31) == 0) { red[0][c >> 5] = p0; red[1][c >> 5] = p1; }
    __syncthreads();
    if (c == 0) {
        out[g * 2 + 0] = red[0][0] + red[0][1] + red[0][2] + red[0][3] + bcls[0];
        out[g * 2 + 1] = red[1][0] + red[1][1] + red[1][2] + red[1][3] + bcls[1];
    }
}

// ---------------- launch ------------------------------------------------------
extern "C" void kernel_launch(void* const* d_in, const int* in_sizes, int n_in,
                              void* d_out, int out_size)
{
    const float* x     = (const float*)d_in[0];
    const int*   eidx  = (const int*)d_in[1];
    const int*   src   = eidx;
    const int*   tgt   = eidx + N_EDGES;
    const int*   root  = (const int*)d_in[2];
    const int*   batch = (const int*)d_in[3];
    const float* wl[4] = {(const float*)d_in[4],  (const float*)d_in[7],
                          (const float*)d_in[10], (const float*)d_in[13]};
    const float* bl[4] = {(const float*)d_in[5],  (const float*)d_in[8],
                          (const float*)d_in[11], (const float*)d_in[14]};
    const float* wr[4] = {(const float*)d_in[6],  (const float*)d_in[9],
                          (const float*)d_in[12], (const float*)d_in[15]};
    const float* wcls  = (const float*)d_in[16];
    const float* bcls  = (const float*)d_in[17];
    float* out = (float*)d_out;

    (void)in_sizes; (void)n_in; (void)out_size;

    static bool attr_set = false;
    static void *p_deg = nullptr, *p_fill = nullptr, *p_gsum = nullptr, *p_gcnt = nullptr;
    if (!attr_set) {
        cudaFuncSetAttribute(k_gemm, cudaFuncAttributeMaxDynamicSharedMemorySize, GEMM_SMEM_B);
        cudaGetSymbolAddress(&p_deg,  d_deg);
        cudaGetSymbolAddress(&p_fill, d_fill);
        cudaGetSymbolAddress(&p_gsum, d_gsum);
        cudaGetSymbolAddress(&p_gcnt, d_gcnt);
        attr_set = true;
    }

    cudaMemsetAsync(p_deg,  0, N_NODES * sizeof(int));
    cudaMemsetAsync(p_fill, 0, N_NODES * sizeof(int));
    cudaMemsetAsync(p_gsum, 0, N_GRAPHS * C * sizeof(float));
    cudaMemsetAsync(p_gcnt, 0, N_GRAPHS * sizeof(float));

    // 1-3: structure build
    k_prep<<<HB + XB + WB, 256>>>(tgt, x,
                                  wl[0], wr[0], wl[1], wr[1],
                                  wl[2], wr[2], wl[3], wr[3]);
    k_scan<<<1, 1024>>>();
    k_fill<<<(N_EDGES + 255) / 256, 256>>>(src, tgt);

    const int AGG_GRID = (N_NODES + 7) / 8;       // 6250

    // layers (launch 4 = first k_agg -> ncu capture slot)
    k_agg<<<AGG_GRID, 256>>>(x, 0);
    k_gemm<<<GGRID, 512, GEMM_SMEM_B>>>(0, 1, 0, bl[0]);
    k_agg<<<AGG_GRID, 256>>>(x, 1);
    k_gemm<<<GGRID, 512, GEMM_SMEM_B>>>(1, 2, 1, bl[1]);
    k_agg<<<AGG_GRID, 256>>>(x, 2);
    k_gemm<<<GGRID, 512, GEMM_SMEM_B>>>(2, 1, 2, bl[2]);
    k_agg<<<AGG_GRID, 256>>>(x, 1);
    k_gemm<<<GGRID, 512, GEMM_SMEM_B>>>(1, 2, 3, bl[3]);

    // readout
    k_pool<<<N_NODES, 128>>>(batch);
    k_final<<<N_GRAPHS, 128>>>(root, wcls, bcls, out);
}